// round 12
// baseline (speedup 1.0000x reference)
#include <cuda_runtime.h>
#include <cstdint>

#define T_SEQ 512
#define H 32
#define GSTEP 16   // steps per tile group
#define SPB 3      // sequences (consumer warps) per block; warp SPB = producer
#define NGRP (T_SEQ / GSTEP)

typedef unsigned long long u64;

__device__ __forceinline__ u64 fma2(u64 a, u64 b, u64 c) {
    u64 d;
    asm("fma.rn.f32x2 %0, %1, %2, %3;" : "=l"(d) : "l"(a), "l"(b), "l"(c));
    return d;
}
__device__ __forceinline__ u64 add2(u64 a, u64 b) {
    u64 d;
    asm("add.rn.f32x2 %0, %1, %2;" : "=l"(d) : "l"(a), "l"(b));
    return d;
}
__device__ __forceinline__ u64 pack2(float lo, float hi) {
    u64 d;
    asm("mov.b64 %0, {%1, %2};" : "=l"(d) : "f"(lo), "f"(hi));
    return d;
}
__device__ __forceinline__ float lo_hi_sum(u64 a) {
    unsigned lo, hi;
    asm("mov.b64 {%0,%1}, %2;" : "=r"(lo), "=r"(hi) : "l"(a));
    return __uint_as_float(lo) + __uint_as_float(hi);
}
__device__ __forceinline__ float tanh_mufu(float x) {
    float y;
    asm("tanh.approx.f32 %0, %1;" : "=f"(y) : "f"(x));
    return y;
}

// ============================================================================
// Single fused kernel. Block = 4 warps:
//   warps 0..2 (consumers): R9-style layer-pipelined recurrence, one sequence
//     each, half-j split, intra-warp syncwarp per step.
//   warp 3 (producer): computes xin = x@W_ih1^T + b1 for all 3 sequences,
//     one 16-step tile group ahead, into double-buffered smem.
// One __syncthreads per GROUP (16 steps) joins producer and consumers.
// ============================================================================
__global__ __launch_bounds__(128, 4)
void rnn_pc_kernel(const float* __restrict__ x,
                   const float* __restrict__ W_ih1,
                   const float* __restrict__ W_hh1,
                   const float* __restrict__ b_ih1,
                   const float* __restrict__ b_hh1,
                   const float* __restrict__ W_ih2,
                   const float* __restrict__ W_hh2,
                   const float* __restrict__ b_ih2,
                   const float* __restrict__ b_hh2,
                   const float* __restrict__ W_fc,
                   const float* __restrict__ b_fc,
                   float* __restrict__ out, int Bn)
{
    const int tid  = threadIdx.x;
    const int wid  = tid >> 5;
    const int lane = tid & 31;
    const int jh   = lane >> 4;
    const int u0   = lane & 15;
    const int base = blockIdx.x * SPB;

    __shared__ __align__(16) float s_h[SPB][2][2 * H];            // h ping-pong
    __shared__ __align__(16) float s_tile[SPB][2][GSTEP][H];      // xin tiles
    __shared__ __align__(16) float s_x0[SPB][H];                  // xin at t=0
    __shared__ __align__(16) float s_stage[SPB][GSTEP][H];        // raw x staging

    // ---- consumer per-warp state (loaded only by consumer warps) ----
    u64 wa0[8], wa1[8], wc0[8], wc1[8], wd0[8], wd1[8];
    float bias2 = 0.0f;
    const int b = base + wid;                    // consumer's sequence
    const bool cons_act = (wid < SPB) && (b < Bn);
    if (cons_act) {
        const int off = jh * 16;
        const u64* p;
        p = (const u64*)(W_hh1 + u0 * H + off);
        #pragma unroll
        for (int k = 0; k < 8; k++) wa0[k] = p[k];
        p = (const u64*)(W_hh1 + (u0 + 16) * H + off);
        #pragma unroll
        for (int k = 0; k < 8; k++) wa1[k] = p[k];
        p = (const u64*)(W_ih2 + u0 * H + off);
        #pragma unroll
        for (int k = 0; k < 8; k++) wc0[k] = p[k];
        p = (const u64*)(W_ih2 + (u0 + 16) * H + off);
        #pragma unroll
        for (int k = 0; k < 8; k++) wc1[k] = p[k];
        p = (const u64*)(W_hh2 + u0 * H + off);
        #pragma unroll
        for (int k = 0; k < 8; k++) wd0[k] = p[k];
        p = (const u64*)(W_hh2 + (u0 + 16) * H + off);
        #pragma unroll
        for (int k = 0; k < 8; k++) wd1[k] = p[k];
        bias2 = b_ih2[lane] + b_hh2[lane];
    }

    // ---- producer state ----
    u64 wp[16];
    u64 bias1p = 0ull;
    if (wid == SPB) {
        const u64* p = (const u64*)(W_ih1 + lane * H);
        #pragma unroll
        for (int k = 0; k < 16; k++) wp[k] = p[k];
        bias1p = pack2(b_ih1[lane] + b_hh1[lane], 0.0f);
    }

    // ---- prologue: producer fills s_x0 and tile group 0 ----
    if (wid == SPB) {
        // stage x rows t=0 for each valid sequence
        #pragma unroll
        for (int s = 0; s < SPB; s++)
            if (base + s < Bn)
                s_stage[s][0][lane] = x[(size_t)(base + s) * T_SEQ * H + lane];
        __syncwarp();
        #pragma unroll
        for (int s = 0; s < SPB; s++)
            if (base + s < Bn) {
                const ulonglong2* xv = (const ulonglong2*)&s_stage[s][0][0];
                u64 a0 = bias1p, a1 = 0ull;
                #pragma unroll
                for (int m = 0; m < 8; m++) {
                    ulonglong2 v = xv[m];
                    a0 = fma2(v.x, wp[2 * m],     a0);
                    a1 = fma2(v.y, wp[2 * m + 1], a1);
                }
                s_x0[s][lane] = lo_hi_sum(add2(a0, a1));
            }
        __syncwarp();
        // stage rows t=1..16 and compute tile group 0
        #pragma unroll
        for (int s = 0; s < SPB; s++)
            if (base + s < Bn) {
                const float* xb = x + (size_t)(base + s) * T_SEQ * H;
                #pragma unroll
                for (int r = 0; r < GSTEP; r++)
                    s_stage[s][r][lane] = xb[(size_t)(1 + r) * H + lane];
            }
        __syncwarp();
        #pragma unroll
        for (int s = 0; s < SPB; s++)
            if (base + s < Bn) {
                #pragma unroll 2
                for (int r = 0; r < GSTEP; r++) {
                    const ulonglong2* xv = (const ulonglong2*)&s_stage[s][r][0];
                    u64 a0 = bias1p, a1 = 0ull;
                    #pragma unroll
                    for (int m = 0; m < 8; m++) {
                        ulonglong2 v = xv[m];
                        a0 = fma2(v.x, wp[2 * m],     a0);
                        a1 = fma2(v.y, wp[2 * m + 1], a1);
                    }
                    s_tile[s][0][r][lane] = lo_hi_sum(add2(a0, a1));
                }
            }
    }
    __syncthreads();

    // consumers publish initial state: h1_0 = tanh(xin_0), h2_{-1} = 0
    if (cons_act) {
        s_h[wid][1][lane]     = tanh_mufu(s_x0[wid][lane]);
        s_h[wid][1][H + lane] = 0.0f;
        __syncwarp();
    }

    float h2last = 0.0f;

    // ---- main loop: one __syncthreads per 16-step group ----
    for (int g = 0; g < NGRP; ++g) {
        if (wid == SPB) {
            // produce tile group g+1 (skipped on last group)
            if (g < NGRP - 1) {
                const int tb = (g + 1) * GSTEP + 1;
                #pragma unroll
                for (int s = 0; s < SPB; s++)
                    if (base + s < Bn) {
                        const float* xb = x + (size_t)(base + s) * T_SEQ * H;
                        #pragma unroll
                        for (int r = 0; r < GSTEP; r++) {
                            int t = tb + r; if (t > T_SEQ - 1) t = T_SEQ - 1;
                            s_stage[s][r][lane] = xb[(size_t)t * H + lane];
                        }
                    }
                __syncwarp();
                const int nbuf = (g + 1) & 1;
                #pragma unroll
                for (int s = 0; s < SPB; s++)
                    if (base + s < Bn) {
                        #pragma unroll 2
                        for (int r = 0; r < GSTEP; r++) {
                            const ulonglong2* xv = (const ulonglong2*)&s_stage[s][r][0];
                            u64 a0 = bias1p, a1 = 0ull;
                            #pragma unroll
                            for (int m = 0; m < 8; m++) {
                                ulonglong2 v = xv[m];
                                a0 = fma2(v.x, wp[2 * m],     a0);
                                a1 = fma2(v.y, wp[2 * m + 1], a1);
                            }
                            s_tile[s][nbuf][r][lane] = lo_hi_sum(add2(a0, a1));
                        }
                    }
            }
        } else if (cons_act) {
            const int buf = g & 1;
            #pragma unroll 2
            for (int kk = 0; kk < GSTEP; ++kk) {
                const int p = kk & 1;    // g*16 even -> parity of k == kk
                const float* sq = &s_h[wid][p ^ 1][jh * 16];
                const ulonglong2* h1v = (const ulonglong2*)(sq);
                const ulonglong2* h2v = (const ulonglong2*)(sq + H);

                const float xinA = s_tile[wid][buf][kk][lane];

                u64 a0 = 0ull, a1 = 0ull, c0 = 0ull, c1 = 0ull;
                #pragma unroll
                for (int m = 0; m < 4; m++) {
                    ulonglong2 v = h1v[m];
                    a0 = fma2(v.x, wa0[2 * m],     a0);
                    a0 = fma2(v.y, wa0[2 * m + 1], a0);
                    a1 = fma2(v.x, wa1[2 * m],     a1);
                    a1 = fma2(v.y, wa1[2 * m + 1], a1);
                    c0 = fma2(v.x, wc0[2 * m],     c0);
                    c0 = fma2(v.y, wc0[2 * m + 1], c0);
                    c1 = fma2(v.x, wc1[2 * m],     c1);
                    c1 = fma2(v.y, wc1[2 * m + 1], c1);
                }
                #pragma unroll
                for (int m = 0; m < 4; m++) {
                    ulonglong2 v = h2v[m];
                    c0 = fma2(v.x, wd0[2 * m],     c0);
                    c0 = fma2(v.y, wd0[2 * m + 1], c0);
                    c1 = fma2(v.x, wd1[2 * m],     c1);
                    c1 = fma2(v.y, wd1[2 * m + 1], c1);
                }

                float sa0 = lo_hi_sum(a0), sa1 = lo_hi_sum(a1);
                float sc0 = lo_hi_sum(c0), sc1 = lo_hi_sum(c1);

                float fa0 = sa0 + __shfl_xor_sync(0xFFFFFFFFu, sa0, 16);
                float fa1 = sa1 + __shfl_xor_sync(0xFFFFFFFFu, sa1, 16);
                float fc0 = sc0 + __shfl_xor_sync(0xFFFFFFFFu, sc0, 16);
                float fc1 = sc1 + __shfl_xor_sync(0xFFFFFFFFu, sc1, 16);

                const float h1n = tanh_mufu((jh ? fa1 : fa0) + xinA);
                const float h2n = tanh_mufu((jh ? fc1 : fc0) + bias2);

                s_h[wid][p][lane]     = h1n;
                s_h[wid][p][H + lane] = h2n;
                __syncwarp();

                h2last = h2n;
            }
        }
        __syncthreads();
    }

    // ---- FC head (consumer warps) ----
    if (cons_act) {
        float v = h2last * W_fc[lane];
        #pragma unroll
        for (int o = 16; o; o >>= 1) v += __shfl_xor_sync(0xFFFFFFFFu, v, o);
        if (lane == 0) out[b] = v + b_fc[0];
    }
}

extern "C" void kernel_launch(void* const* d_in, const int* in_sizes, int n_in,
                              void* d_out, int out_size)
{
    const float* x     = (const float*)d_in[0];
    const float* W_ih1 = (const float*)d_in[1];
    const float* W_hh1 = (const float*)d_in[2];
    const float* b_ih1 = (const float*)d_in[3];
    const float* b_hh1 = (const float*)d_in[4];
    const float* W_ih2 = (const float*)d_in[5];
    const float* W_hh2 = (const float*)d_in[6];
    const float* b_ih2 = (const float*)d_in[7];
    const float* b_hh2 = (const float*)d_in[8];
    const float* W_fc  = (const float*)d_in[9];
    const float* b_fc  = (const float*)d_in[10];
    float* out = (float*)d_out;

    const int Bn = in_sizes[0] / (T_SEQ * H);
    const int nblk = (Bn + SPB - 1) / SPB;

    rnn_pc_kernel<<<nblk, 128>>>(x, W_ih1, W_hh1, b_ih1, b_hh1,
                                 W_ih2, W_hh2, b_ih2, b_hh2,
                                 W_fc, b_fc, out, Bn);
}

// round 13
// speedup vs baseline: 1.0028x; 1.0028x over previous
#include <cuda_runtime.h>
#include <cstdint>

#define T_SEQ 512
#define H 32
#define MAXB 4096
#define GSTEP 16   // xin tile depth (steps per prefetch group)

typedef unsigned long long u64;

// scratch: xin[b][t][i]; +24 rows pad so tile prefetch may overrun.
__device__ float g_xin[((size_t)MAXB * T_SEQ + 24) * H];

__device__ __forceinline__ u64 fma2(u64 a, u64 b, u64 c) {
    u64 d;
    asm("fma.rn.f32x2 %0, %1, %2, %3;" : "=l"(d) : "l"(a), "l"(b), "l"(c));
    return d;
}
__device__ __forceinline__ u64 add2(u64 a, u64 b) {
    u64 d;
    asm("add.rn.f32x2 %0, %1, %2;" : "=l"(d) : "l"(a), "l"(b));
    return d;
}
__device__ __forceinline__ u64 pack2(float lo, float hi) {
    u64 d;
    asm("mov.b64 %0, {%1, %2};" : "=l"(d) : "f"(lo), "f"(hi));
    return d;
}
__device__ __forceinline__ float lo_hi_sum(u64 a) {
    unsigned lo, hi;
    asm("mov.b64 {%0,%1}, %2;" : "=r"(lo), "=r"(hi) : "l"(a));
    return __uint_as_float(lo) + __uint_as_float(hi);
}
__device__ __forceinline__ float tanh_mufu(float x) {
    float y;
    asm("tanh.approx.f32 %0, %1;" : "=f"(y) : "f"(x));
    return y;
}

// ============================================================================
// K1: xin precompute. 32 rows/warp (2x warp count vs R9) for latency hiding.
// W staged via padded shared; x broadcast via uniform LDS; coalesced LDG/STG.
// ============================================================================
__global__ __launch_bounds__(128)
void xin_kernel(const float* __restrict__ x,
                const float* __restrict__ W_ih1,
                const float* __restrict__ b_ih1,
                const float* __restrict__ b_hh1)
{
    const int tid  = threadIdx.x;
    const int lane = tid & 31;
    const int wid  = tid >> 5;

    __shared__ __align__(16) float sw[32][36];
    __shared__ __align__(16) float sx[4][2][8 * H];

    #pragma unroll
    for (int idx = tid; idx < H * H; idx += 128) sw[idx >> 5][idx & 31] = W_ih1[idx];
    __syncthreads();

    u64 w[16];
    {
        const u64* wr = (const u64*)&sw[lane][0];
        #pragma unroll
        for (int k = 0; k < 16; k++) w[k] = wr[k];
    }
    const u64 biasp = pack2(b_ih1[lane] + b_hh1[lane], 0.0f);

    const long long base = ((long long)blockIdx.x * 4 + wid) * 32;  // 32 rows/warp
    const float* xb = x + base * H;
    float* ob = g_xin + base * H;

    float4 p0 = *(const float4*)(xb + lane * 4);
    float4 p1 = *(const float4*)(xb + 128 + lane * 4);

    #pragma unroll
    for (int g = 0; g < 4; g++) {
        const int buf = g & 1;
        *(float4*)&sx[wid][buf][lane * 4]       = p0;
        *(float4*)&sx[wid][buf][128 + lane * 4] = p1;
        if (g < 3) {
            p0 = *(const float4*)(xb + (g + 1) * 256 + lane * 4);
            p1 = *(const float4*)(xb + (g + 1) * 256 + 128 + lane * 4);
        }
        __syncwarp();

        #pragma unroll
        for (int rr = 0; rr < 8; rr += 2) {
            const ulonglong2* xv0 = (const ulonglong2*)&sx[wid][buf][rr * H];
            const ulonglong2* xv1 = (const ulonglong2*)&sx[wid][buf][(rr + 1) * H];
            u64 a0 = biasp, a1 = 0ull, b0 = biasp, b1 = 0ull;
            #pragma unroll
            for (int m = 0; m < 8; m++) {
                ulonglong2 v0 = xv0[m];
                ulonglong2 v1 = xv1[m];
                a0 = fma2(v0.x, w[2 * m],     a0);
                a1 = fma2(v0.y, w[2 * m + 1], a1);
                b0 = fma2(v1.x, w[2 * m],     b0);
                b1 = fma2(v1.y, w[2 * m + 1], b1);
            }
            ob[(g * 8 + rr)     * H + lane] = lo_hi_sum(add2(a0, a1));
            ob[(g * 8 + rr + 1) * H + lane] = lo_hi_sum(add2(b0, b1));
        }
    }
}

// ============================================================================
// K2: R9 core (layer-pipelined, 1 seq/warp, half-j split, GSTEP smem tile)
// with: directed half-exchange (2 shfls/step instead of 4) and
// __launch_bounds__(32,17) to push residency to 17 warps/SM.
//   h1_{k+1} = tanh(W_hh1 h1_k + xin_{k+1})
//   h2_k     = tanh(W_ih2 h1_k + W_hh2 h2_{k-1} + b2)
// ============================================================================
__global__ __launch_bounds__(32, 17)
void rnn_rec_kernel(const float* __restrict__ W_hh1,
                    const float* __restrict__ W_ih2,
                    const float* __restrict__ W_hh2,
                    const float* __restrict__ b_ih2,
                    const float* __restrict__ b_hh2,
                    const float* __restrict__ W_fc,
                    const float* __restrict__ b_fc,
                    float* __restrict__ out, int Bn)
{
    const int lane = threadIdx.x & 31;
    const int jh   = lane >> 4;        // j-half this lane reads
    const int u0   = lane & 15;        // unit pair (u0, u0+16); lane finalizes unit==lane
    const int b    = blockIdx.x;
    if (b >= Bn) return;

    __shared__ __align__(16) float s[2][2 * H];     // h ping-pong [buf][h1|h2]
    __shared__ float sx[2][GSTEP][32];              // xin tile [buf][d][lane]

    u64 w1_0[8], w1_1[8], w2_0[8], w2_1[8], w3_0[8], w3_1[8];
    {
        const int off = jh * 16;
        const u64* p;
        p = (const u64*)(W_hh1 + u0 * H + off);
        #pragma unroll
        for (int k = 0; k < 8; k++) w1_0[k] = p[k];
        p = (const u64*)(W_hh1 + (u0 + 16) * H + off);
        #pragma unroll
        for (int k = 0; k < 8; k++) w1_1[k] = p[k];
        p = (const u64*)(W_ih2 + u0 * H + off);
        #pragma unroll
        for (int k = 0; k < 8; k++) w2_0[k] = p[k];
        p = (const u64*)(W_ih2 + (u0 + 16) * H + off);
        #pragma unroll
        for (int k = 0; k < 8; k++) w2_1[k] = p[k];
        p = (const u64*)(W_hh2 + u0 * H + off);
        #pragma unroll
        for (int k = 0; k < 8; k++) w3_0[k] = p[k];
        p = (const u64*)(W_hh2 + (u0 + 16) * H + off);
        #pragma unroll
        for (int k = 0; k < 8; k++) w3_1[k] = p[k];
    }
    const float bias2 = b_ih2[lane] + b_hh2[lane];  // per finalized unit (== lane)

    const float* xA = g_xin + (size_t)b * T_SEQ * H + lane;

    // prologue: h1_0 = tanh(xin_0) (xin carries b1), h2_{-1}=0, in buffer 1
    s[1][lane]     = tanh_mufu(xA[0]);
    s[1][H + lane] = 0.0f;
    __syncwarp();

    // preload tile group 0 (steps k=0..15 -> t=1..16)
    #pragma unroll
    for (int d = 0; d < GSTEP; d++)
        sx[0][d][lane] = xA[(size_t)(d + 1) * H];

    float h2A = 0.0f;

    for (int g = 0; g < T_SEQ / GSTEP; ++g) {
        const int buf = g & 1;
        // burst-prefetch next tile (overrun absorbed by g_xin pad)
        {
            const size_t tb = (size_t)(g + 1) * GSTEP + 1;
            #pragma unroll
            for (int d = 0; d < GSTEP; d++)
                sx[buf ^ 1][d][lane] = xA[(tb + d) * H];
        }

        #pragma unroll 2
        for (int kk = 0; kk < GSTEP; ++kk) {
            const int p = kk & 1;
            const float* sq = &s[p ^ 1][jh * 16];
            const ulonglong2* h1v = (const ulonglong2*)(sq);
            const ulonglong2* h2v = (const ulonglong2*)(sq + H);

            const float xinA = sx[buf][kk][lane];

            u64 a0 = 0ull, a1 = 0ull, c0 = 0ull, c1 = 0ull;

            #pragma unroll
            for (int m = 0; m < 4; m++) {
                ulonglong2 v = h1v[m];
                a0 = fma2(v.x, w1_0[2 * m],     a0);
                a0 = fma2(v.y, w1_0[2 * m + 1], a0);
                a1 = fma2(v.x, w1_1[2 * m],     a1);
                a1 = fma2(v.y, w1_1[2 * m + 1], a1);
                c0 = fma2(v.x, w2_0[2 * m],     c0);
                c0 = fma2(v.y, w2_0[2 * m + 1], c0);
                c1 = fma2(v.x, w2_1[2 * m],     c1);
                c1 = fma2(v.y, w2_1[2 * m + 1], c1);
            }
            #pragma unroll
            for (int m = 0; m < 4; m++) {
                ulonglong2 v = h2v[m];
                c0 = fma2(v.x, w3_0[2 * m],     c0);
                c0 = fma2(v.y, w3_0[2 * m + 1], c0);
                c1 = fma2(v.x, w3_1[2 * m],     c1);
                c1 = fma2(v.y, w3_1[2 * m + 1], c1);
            }

            float sa0 = lo_hi_sum(a0), sa1 = lo_hi_sum(a1);
            float sc0 = lo_hi_sum(c0), sc1 = lo_hi_sum(c1);

            // directed exchange: send the partial the PARTNER finalizes.
            // jh=0 finalizes u0 (needs partner sa0/sc0, sends sa1/sc1);
            // jh=1 finalizes u0+16 (needs partner sa1/sc1, sends sa0/sc0).
            float sendA = jh ? sa0 : sa1;
            float sendC = jh ? sc0 : sc1;
            float recvA = __shfl_xor_sync(0xFFFFFFFFu, sendA, 16);
            float recvC = __shfl_xor_sync(0xFFFFFFFFu, sendC, 16);
            float keepA = jh ? sa1 : sa0;
            float keepC = jh ? sc1 : sc0;

            const float h1n = tanh_mufu(keepA + recvA + xinA);
            const float h2n = tanh_mufu(keepC + recvC + bias2);

            s[p][lane]     = h1n;
            s[p][H + lane] = h2n;
            __syncwarp();

            h2A = h2n;
        }
    }

    float v = h2A * W_fc[lane];
    #pragma unroll
    for (int o = 16; o; o >>= 1) v += __shfl_xor_sync(0xFFFFFFFFu, v, o);
    if (lane == 0) out[b] = v + b_fc[0];
}

extern "C" void kernel_launch(void* const* d_in, const int* in_sizes, int n_in,
                              void* d_out, int out_size)
{
    const float* x     = (const float*)d_in[0];
    const float* W_ih1 = (const float*)d_in[1];
    const float* W_hh1 = (const float*)d_in[2];
    const float* b_ih1 = (const float*)d_in[3];
    const float* b_hh1 = (const float*)d_in[4];
    const float* W_ih2 = (const float*)d_in[5];
    const float* W_hh2 = (const float*)d_in[6];
    const float* b_ih2 = (const float*)d_in[7];
    const float* b_hh2 = (const float*)d_in[8];
    const float* W_fc  = (const float*)d_in[9];
    const float* b_fc  = (const float*)d_in[10];
    float* out = (float*)d_out;

    const int Bn = in_sizes[0] / (T_SEQ * H);

    // K1: 128 rows/block (4 warps x 32 rows); rows is a multiple of 128
    const int rows = Bn * T_SEQ;
    xin_kernel<<<rows / 128, 128>>>(x, W_ih1, b_ih1, b_hh1);

    // K2: one warp per sequence
    rnn_rec_kernel<<<Bn, 32>>>(
        W_hh1, W_ih2, W_hh2, b_ih2, b_hh2, W_fc, b_fc, out, Bn);
}

// round 14
// speedup vs baseline: 2.2918x; 2.2854x over previous
#include <cuda_runtime.h>
#include <cstdint>

#define T_SEQ 512
#define H 32
#define MAXB 4096
#define GSTEP 16   // xin tile depth (steps per prefetch group)

typedef unsigned long long u64;

// scratch: xin[b][t][i]; +24 rows pad so tile prefetch may overrun.
__device__ float g_xin[((size_t)MAXB * T_SEQ + 24) * H];

__device__ __forceinline__ u64 fma2(u64 a, u64 b, u64 c) {
    u64 d;
    asm("fma.rn.f32x2 %0, %1, %2, %3;" : "=l"(d) : "l"(a), "l"(b), "l"(c));
    return d;
}
__device__ __forceinline__ u64 add2(u64 a, u64 b) {
    u64 d;
    asm("add.rn.f32x2 %0, %1, %2;" : "=l"(d) : "l"(a), "l"(b));
    return d;
}
__device__ __forceinline__ u64 pack2(float lo, float hi) {
    u64 d;
    asm("mov.b64 %0, {%1, %2};" : "=l"(d) : "f"(lo), "f"(hi));
    return d;
}
__device__ __forceinline__ float lo_hi_sum(u64 a) {
    unsigned lo, hi;
    asm("mov.b64 {%0,%1}, %2;" : "=r"(lo), "=r"(hi) : "l"(a));
    return __uint_as_float(lo) + __uint_as_float(hi);
}
__device__ __forceinline__ float tanh_mufu(float x) {
    float y;
    asm("tanh.approx.f32 %0, %1;" : "=f"(y) : "f"(x));
    return y;
}
__device__ __forceinline__ float tanh_fast(float x) {
    float e = __expf(2.0f * x);
    return 1.0f - __fdividef(2.0f, e + 1.0f);
}

// ============================================================================
// K1: xin precompute — byte-identical to round 9 (64 rows/warp, ~148us).
// ============================================================================
__global__ __launch_bounds__(128)
void xin_kernel(const float* __restrict__ x,
                const float* __restrict__ W_ih1,
                const float* __restrict__ b_ih1,
                const float* __restrict__ b_hh1)
{
    const int tid  = threadIdx.x;
    const int lane = tid & 31;
    const int wid  = tid >> 5;

    __shared__ __align__(16) float sw[32][36];
    __shared__ __align__(16) float sx[4][2][8 * H];

    #pragma unroll
    for (int idx = tid; idx < H * H; idx += 128) sw[idx >> 5][idx & 31] = W_ih1[idx];
    __syncthreads();

    u64 w[16];
    {
        const u64* wr = (const u64*)&sw[lane][0];
        #pragma unroll
        for (int k = 0; k < 16; k++) w[k] = wr[k];
    }
    const u64 biasp = pack2(b_ih1[lane] + b_hh1[lane], 0.0f);

    const long long base = ((long long)blockIdx.x * 4 + wid) * 64;
    const float* xb = x + base * H;
    float* ob = g_xin + base * H;

    float4 p0 = *(const float4*)(xb + lane * 4);
    float4 p1 = *(const float4*)(xb + 128 + lane * 4);

    #pragma unroll
    for (int g = 0; g < 8; g++) {
        const int buf = g & 1;
        *(float4*)&sx[wid][buf][lane * 4]       = p0;
        *(float4*)&sx[wid][buf][128 + lane * 4] = p1;
        if (g < 7) {
            p0 = *(const float4*)(xb + (g + 1) * 256 + lane * 4);
            p1 = *(const float4*)(xb + (g + 1) * 256 + 128 + lane * 4);
        }
        __syncwarp();

        #pragma unroll
        for (int rr = 0; rr < 8; rr += 2) {
            const ulonglong2* xv0 = (const ulonglong2*)&sx[wid][buf][rr * H];
            const ulonglong2* xv1 = (const ulonglong2*)&sx[wid][buf][(rr + 1) * H];
            u64 a0 = biasp, a1 = 0ull, b0 = biasp, b1 = 0ull;
            #pragma unroll
            for (int m = 0; m < 8; m++) {
                ulonglong2 v0 = xv0[m];
                ulonglong2 v1 = xv1[m];
                a0 = fma2(v0.x, w[2 * m],     a0);
                a1 = fma2(v0.y, w[2 * m + 1], a1);
                b0 = fma2(v1.x, w[2 * m],     b0);
                b1 = fma2(v1.y, w[2 * m + 1], b1);
            }
            ob[(g * 8 + rr)     * H + lane] = lo_hi_sum(add2(a0, a1));
            ob[(g * 8 + rr + 1) * H + lane] = lo_hi_sum(add2(b0, b1));
        }
    }
}

// ============================================================================
// K2: R9 core EXACTLY (layer-pipelined, 1 seq/warp, half-j split, GSTEP tile,
// __launch_bounds__(32,16) -> 128 regs, NO forced cap) with the directed
// half-exchange as the only change (2 shfl + 2 add per step instead of 4+4).
//   h1_{k+1} = tanh(W_hh1 h1_k + xin_{k+1})
//   h2_k     = tanh(W_ih2 h1_k + W_hh2 h2_{k-1} + b2)
// ============================================================================
__global__ __launch_bounds__(32, 16)
void rnn_rec_kernel(const float* __restrict__ W_hh1,
                    const float* __restrict__ W_ih2,
                    const float* __restrict__ W_hh2,
                    const float* __restrict__ b_ih2,
                    const float* __restrict__ b_hh2,
                    const float* __restrict__ W_fc,
                    const float* __restrict__ b_fc,
                    float* __restrict__ out, int Bn)
{
    const int lane = threadIdx.x & 31;
    const int jh   = lane >> 4;        // j-half this lane reads
    const int u0   = lane & 15;        // unit pair (u0, u0+16); lane finalizes unit==lane
    const int b    = blockIdx.x;
    if (b >= Bn) return;

    __shared__ __align__(16) float s[2][2 * H];     // h ping-pong [buf][h1|h2]
    __shared__ float sx[2][GSTEP][32];              // xin tile [buf][d][lane]

    u64 w1_0[8], w1_1[8], w2_0[8], w2_1[8], w3_0[8], w3_1[8];
    {
        const int off = jh * 16;
        const u64* p;
        p = (const u64*)(W_hh1 + u0 * H + off);
        #pragma unroll
        for (int k = 0; k < 8; k++) w1_0[k] = p[k];
        p = (const u64*)(W_hh1 + (u0 + 16) * H + off);
        #pragma unroll
        for (int k = 0; k < 8; k++) w1_1[k] = p[k];
        p = (const u64*)(W_ih2 + u0 * H + off);
        #pragma unroll
        for (int k = 0; k < 8; k++) w2_0[k] = p[k];
        p = (const u64*)(W_ih2 + (u0 + 16) * H + off);
        #pragma unroll
        for (int k = 0; k < 8; k++) w2_1[k] = p[k];
        p = (const u64*)(W_hh2 + u0 * H + off);
        #pragma unroll
        for (int k = 0; k < 8; k++) w3_0[k] = p[k];
        p = (const u64*)(W_hh2 + (u0 + 16) * H + off);
        #pragma unroll
        for (int k = 0; k < 8; k++) w3_1[k] = p[k];
    }
    const float bias2 = b_ih2[lane] + b_hh2[lane];  // per finalized unit (== lane)

    const float* xA = g_xin + (size_t)b * T_SEQ * H + lane;

    // prologue: h1_0 = tanh(xin_0) (xin carries b1), h2_{-1}=0, in buffer 1
    s[1][lane]     = tanh_fast(xA[0]);
    s[1][H + lane] = 0.0f;
    __syncwarp();

    // preload tile group 0 (steps k=0..15 -> t=1..16)
    #pragma unroll
    for (int d = 0; d < GSTEP; d++)
        sx[0][d][lane] = xA[(size_t)(d + 1) * H];

    float h2A = 0.0f;

    for (int g = 0; g < T_SEQ / GSTEP; ++g) {
        const int buf = g & 1;
        // burst-prefetch next tile (overrun absorbed by g_xin pad)
        {
            const size_t tb = (size_t)(g + 1) * GSTEP + 1;
            #pragma unroll
            for (int d = 0; d < GSTEP; d++)
                sx[buf ^ 1][d][lane] = xA[(tb + d) * H];
        }

        #pragma unroll 2
        for (int kk = 0; kk < GSTEP; ++kk) {
            const int p = kk & 1;   // g*16 even -> parity of k == parity of kk
            const float* sq = &s[p ^ 1][jh * 16];
            const ulonglong2* h1v = (const ulonglong2*)(sq);
            const ulonglong2* h2v = (const ulonglong2*)(sq + H);

            const float xinA = sx[buf][kk][lane];

            u64 a0 = 0ull, a1 = 0ull, c0 = 0ull, c1 = 0ull;

            #pragma unroll
            for (int m = 0; m < 4; m++) {
                ulonglong2 v = h1v[m];
                a0 = fma2(v.x, w1_0[2 * m],     a0);
                a0 = fma2(v.y, w1_0[2 * m + 1], a0);
                a1 = fma2(v.x, w1_1[2 * m],     a1);
                a1 = fma2(v.y, w1_1[2 * m + 1], a1);
                c0 = fma2(v.x, w2_0[2 * m],     c0);
                c0 = fma2(v.y, w2_0[2 * m + 1], c0);
                c1 = fma2(v.x, w2_1[2 * m],     c1);
                c1 = fma2(v.y, w2_1[2 * m + 1], c1);
            }
            #pragma unroll
            for (int m = 0; m < 4; m++) {
                ulonglong2 v = h2v[m];
                c0 = fma2(v.x, w3_0[2 * m],     c0);
                c0 = fma2(v.y, w3_0[2 * m + 1], c0);
                c1 = fma2(v.x, w3_1[2 * m],     c1);
                c1 = fma2(v.y, w3_1[2 * m + 1], c1);
            }

            float sa0 = lo_hi_sum(a0), sa1 = lo_hi_sum(a1);
            float sc0 = lo_hi_sum(c0), sc1 = lo_hi_sum(c1);

            // directed exchange: send only the partial the PARTNER finalizes.
            // jh=0 finalizes u0 (keeps s*0, sends s*1); jh=1 finalizes u0+16.
            float sendA = jh ? sa0 : sa1;
            float sendC = jh ? sc0 : sc1;
            float recvA = __shfl_xor_sync(0xFFFFFFFFu, sendA, 16);
            float recvC = __shfl_xor_sync(0xFFFFFFFFu, sendC, 16);
            float keepA = jh ? sa1 : sa0;
            float keepC = jh ? sc1 : sc0;

            const float h1n = tanh_mufu(keepA + recvA + xinA);
            const float h2n = tanh_mufu(keepC + recvC + bias2);

            s[p][lane]     = h1n;
            s[p][H + lane] = h2n;
            __syncwarp();

            h2A = h2n;
        }
    }

    float v = h2A * W_fc[lane];
    #pragma unroll
    for (int o = 16; o; o >>= 1) v += __shfl_xor_sync(0xFFFFFFFFu, v, o);
    if (lane == 0) out[b] = v + b_fc[0];
}

extern "C" void kernel_launch(void* const* d_in, const int* in_sizes, int n_in,
                              void* d_out, int out_size)
{
    const float* x     = (const float*)d_in[0];
    const float* W_ih1 = (const float*)d_in[1];
    const float* W_hh1 = (const float*)d_in[2];
    const float* b_ih1 = (const float*)d_in[3];
    const float* b_hh1 = (const float*)d_in[4];
    const float* W_ih2 = (const float*)d_in[5];
    const float* W_hh2 = (const float*)d_in[6];
    const float* b_ih2 = (const float*)d_in[7];
    const float* b_hh2 = (const float*)d_in[8];
    const float* W_fc  = (const float*)d_in[9];
    const float* b_fc  = (const float*)d_in[10];
    float* out = (float*)d_out;

    const int Bn = in_sizes[0] / (T_SEQ * H);

    // K1: 256 rows/block (4 warps x 64 rows)
    const int rows = Bn * T_SEQ;
    xin_kernel<<<rows / 256, 128>>>(x, W_ih1, b_ih1, b_hh1);

    // K2: one warp per sequence
    rnn_rec_kernel<<<Bn, 32>>>(
        W_hh1, W_ih2, W_hh2, b_ih2, b_hh2, W_fc, b_fc, out, Bn);
}